// round 1
// baseline (speedup 1.0000x reference)
#include <cuda_runtime.h>
#include <math.h>

#define NB 8
#define H 256
#define W 256
#define H2 512
#define W2 512
#define HW (H*W)

// ---------------- scratch (device globals; no allocation) ----------------
__device__ float g_curr[NB*3*HW];    // resized right image
__device__ float g_feats[NB*12*HW];  // concat features
__device__ float g_x1[NB*32*HW];     // conv1 out
__device__ float g_x2[NB*64*HW];     // conv2 out
__device__ float g_aff[NB*8*HW];     // conv3 out (affinities)
__device__ float g_s1[32], g_bb1[32], g_s2[64], g_bb2[64]; // folded BN

// ---------------- BN fold ----------------
__global__ void k_bnfold(const float* __restrict__ g1, const float* __restrict__ b1,
                         const float* __restrict__ m1, const float* __restrict__ v1,
                         const float* __restrict__ g2, const float* __restrict__ b2,
                         const float* __restrict__ m2, const float* __restrict__ v2) {
    int i = threadIdx.x;
    if (i < 32) { float s = g1[i] * rsqrtf(v1[i] + 1e-5f); g_s1[i] = s; g_bb1[i] = b1[i] - m1[i] * s; }
    if (i < 64) { float s = g2[i] * rsqrtf(v2[i] + 1e-5f); g_s2[i] = s; g_bb2[i] = b2[i] - m2[i] * s; }
}

// ---------------- resize right (2x2 avg pool) -> g_curr and feats ch 6..8 ----------------
__global__ void k_resize_right(const float* __restrict__ right) {
    int idx = blockIdx.x * blockDim.x + threadIdx.x;
    if (idx >= NB*3*HW) return;
    int x = idx & 255;
    int y = (idx >> 8) & 255;
    int nc = idx >> 16;          // n*3 + c
    int c = nc % 3, n = nc / 3;
    const float* src = right + ((size_t)(n*3 + c) * H2 + 2*y) * W2 + 2*x;
    float v = 0.25f * (src[0] + src[1] + src[W2] + src[W2+1]);
    g_curr[idx] = v;
    g_feats[((size_t)(n*12 + 6 + c) * H + y) * W + x] = v;
}

// ---------------- left resize + normal copy + LR-warp error ----------------
__global__ void k_feats(const float* __restrict__ left, const float* __restrict__ normal,
                        const float* __restrict__ disp) {
    int idx = blockIdx.x * blockDim.x + threadIdx.x;
    if (idx >= NB*3*HW) return;
    int x = idx & 255;
    int y = (idx >> 8) & 255;
    int nc = idx >> 16;
    int c = nc % 3, n = nc / 3;

    const float* srcL = left + ((size_t)(n*3 + c) * H2 + 2*y) * W2 + 2*x;
    float l = 0.25f * (srcL[0] + srcL[1] + srcL[W2] + srcL[W2+1]);

    size_t base = ((size_t)(n*12) * H + y) * W + x;
    g_feats[base + (size_t)c * HW]     = normal[((size_t)(n*3 + c) * H + y) * W + x];
    g_feats[base + (size_t)(3+c) * HW] = l;

    float d = disp[((size_t)n * H + y) * W + x];
    float xs = (float)x - d;
    float x0f = floorf(xs);
    float frac = xs - x0f;
    int x0i = (int)x0f;
    int x1i = x0i + 1;
    float v0 = (x0i >= 0 && x0i < W) ? 1.f : 0.f;
    float v1 = (x1i >= 0 && x1i < W) ? 1.f : 0.f;
    int x0c = min(max(x0i, 0), W-1);
    int x1c = min(max(x1i, 0), W-1);
    const float* r = g_curr + ((size_t)(n*3 + c) * H + y) * W;
    float warped = (r[x0c] * v0) * (1.f - frac) + (r[x1c] * v1) * frac;
    g_feats[base + (size_t)(9+c) * HW] = fabsf(l - warped);
}

// ---------------- conv1: 12 -> 32, 3x3, pad 1, BN+ReLU ----------------
// block 256 thr, tile 32x32 pixels, 8 out-channels per block (grid.z = n*4+cg)
// cin in 2 chunks of 6; each thread: 2x2 pixels x 8 couts
__global__ void __launch_bounds__(256) k_conv1(const float* __restrict__ w) {
    __shared__ float sIn[6][34][34];    // 27.7 KB
    __shared__ float sW[8*12*9];        //  3.5 KB
    int t = threadIdx.x;
    int bz = blockIdx.z;
    int n = bz >> 2, cg = bz & 3;
    int x0 = blockIdx.x * 32, y0 = blockIdx.y * 32;

    for (int i = t; i < 8*12*9; i += 256) sW[i] = w[cg*8*108 + i];

    float acc[8][4];
    #pragma unroll
    for (int co = 0; co < 8; co++) { acc[co][0]=0.f; acc[co][1]=0.f; acc[co][2]=0.f; acc[co][3]=0.f; }

    int tx = t & 15, ty = t >> 4;
    int px = tx * 2, py = ty * 2;

    for (int cc = 0; cc < 2; cc++) {
        __syncthreads();
        for (int i = t; i < 6*34*34; i += 256) {
            int ci = i / 1156; int rem = i % 1156;
            int yy = rem / 34, xx = rem % 34;
            int gy = y0 + yy - 1, gx = x0 + xx - 1;
            float v = 0.f;
            if (gy >= 0 && gy < H && gx >= 0 && gx < W)
                v = g_feats[((size_t)(n*12 + cc*6 + ci) * H + gy) * W + gx];
            sIn[ci][yy][xx] = v;
        }
        __syncthreads();
        for (int ci = 0; ci < 6; ci++) {
            float r[4][4];
            #pragma unroll
            for (int i = 0; i < 4; i++)
                #pragma unroll
                for (int j = 0; j < 4; j++)
                    r[i][j] = sIn[ci][py+i][px+j];
            #pragma unroll
            for (int co = 0; co < 8; co++) {
                const float* wp = &sW[(co*12 + cc*6 + ci) * 9];
                #pragma unroll
                for (int ky = 0; ky < 3; ky++)
                    #pragma unroll
                    for (int kx = 0; kx < 3; kx++) {
                        float wv = wp[ky*3 + kx];
                        acc[co][0] = fmaf(wv, r[ky  ][kx  ], acc[co][0]);
                        acc[co][1] = fmaf(wv, r[ky  ][kx+1], acc[co][1]);
                        acc[co][2] = fmaf(wv, r[ky+1][kx  ], acc[co][2]);
                        acc[co][3] = fmaf(wv, r[ky+1][kx+1], acc[co][3]);
                    }
            }
        }
    }

    #pragma unroll
    for (int co = 0; co < 8; co++) {
        int oc = cg*8 + co;
        float s = g_s1[oc], bo = g_bb1[oc];
        float* o = g_x1 + ((size_t)(n*32 + oc) * H + y0 + py) * W + x0 + px;
        float2 top = make_float2(fmaxf(fmaf(acc[co][0], s, bo), 0.f),
                                 fmaxf(fmaf(acc[co][1], s, bo), 0.f));
        float2 bot = make_float2(fmaxf(fmaf(acc[co][2], s, bo), 0.f),
                                 fmaxf(fmaf(acc[co][3], s, bo), 0.f));
        *reinterpret_cast<float2*>(o)     = top;
        *reinterpret_cast<float2*>(o + W) = bot;
    }
}

// ---------------- conv2: 32 -> 64, 3x3, pad 1, BN+ReLU ----------------
// block 256 thr, tile 32x32, 16 out-channels per block (grid.z = n*4+cg)
// cin in 4 chunks of 8; weights reloaded per chunk to stay < 48 KB static smem
__global__ void __launch_bounds__(256, 2) k_conv2(const float* __restrict__ w) {
    __shared__ float sIn[8][34][34];    // 37.0 KB
    __shared__ float sW[16*8*9];        //  4.6 KB
    int t = threadIdx.x;
    int bz = blockIdx.z;
    int n = bz >> 2, cg = bz & 3;
    int x0 = blockIdx.x * 32, y0 = blockIdx.y * 32;

    float acc[16][4];
    #pragma unroll
    for (int co = 0; co < 16; co++) { acc[co][0]=0.f; acc[co][1]=0.f; acc[co][2]=0.f; acc[co][3]=0.f; }

    int tx = t & 15, ty = t >> 4;
    int px = tx * 2, py = ty * 2;

    for (int cc = 0; cc < 4; cc++) {
        __syncthreads();
        // weights for this chunk: couts cg*16..+15, cins cc*8..+7
        for (int i = t; i < 16*8*9; i += 256) {
            int co = i / 72; int rem = i % 72;
            sW[i] = w[(size_t)(cg*16 + co) * 288 + cc*72 + rem];
        }
        for (int i = t; i < 8*34*34; i += 256) {
            int ci = i / 1156; int rem = i % 1156;
            int yy = rem / 34, xx = rem % 34;
            int gy = y0 + yy - 1, gx = x0 + xx - 1;
            float v = 0.f;
            if (gy >= 0 && gy < H && gx >= 0 && gx < W)
                v = g_x1[((size_t)(n*32 + cc*8 + ci) * H + gy) * W + gx];
            sIn[ci][yy][xx] = v;
        }
        __syncthreads();
        for (int ci = 0; ci < 8; ci++) {
            float r[4][4];
            #pragma unroll
            for (int i = 0; i < 4; i++)
                #pragma unroll
                for (int j = 0; j < 4; j++)
                    r[i][j] = sIn[ci][py+i][px+j];
            #pragma unroll
            for (int co = 0; co < 16; co++) {
                const float* wp = &sW[(co*8 + ci) * 9];
                #pragma unroll
                for (int ky = 0; ky < 3; ky++)
                    #pragma unroll
                    for (int kx = 0; kx < 3; kx++) {
                        float wv = wp[ky*3 + kx];
                        acc[co][0] = fmaf(wv, r[ky  ][kx  ], acc[co][0]);
                        acc[co][1] = fmaf(wv, r[ky  ][kx+1], acc[co][1]);
                        acc[co][2] = fmaf(wv, r[ky+1][kx  ], acc[co][2]);
                        acc[co][3] = fmaf(wv, r[ky+1][kx+1], acc[co][3]);
                    }
            }
        }
    }

    #pragma unroll
    for (int co = 0; co < 16; co++) {
        int oc = cg*16 + co;
        float s = g_s2[oc], bo = g_bb2[oc];
        float* o = g_x2 + ((size_t)(n*64 + oc) * H + y0 + py) * W + x0 + px;
        float2 top = make_float2(fmaxf(fmaf(acc[co][0], s, bo), 0.f),
                                 fmaxf(fmaf(acc[co][1], s, bo), 0.f));
        float2 bot = make_float2(fmaxf(fmaf(acc[co][2], s, bo), 0.f),
                                 fmaxf(fmaf(acc[co][3], s, bo), 0.f));
        *reinterpret_cast<float2*>(o)     = top;
        *reinterpret_cast<float2*>(o + W) = bot;
    }
}

// ---------------- conv3: 1x1, 64 -> 8, ReLU ----------------
// each thread: 4 consecutive pixels, all 8 couts
__global__ void __launch_bounds__(256) k_conv3(const float* __restrict__ w3) {
    __shared__ float sW[512];
    int t = threadIdx.x;
    for (int i = t; i < 512; i += 256) sW[i] = w3[i];
    __syncthreads();

    int idx = blockIdx.x * 256 + t;      // 131072 threads total
    int pix = idx * 4;
    int n = pix / HW;
    int p = pix % HW;

    float acc[8][4];
    #pragma unroll
    for (int co = 0; co < 8; co++) { acc[co][0]=0.f; acc[co][1]=0.f; acc[co][2]=0.f; acc[co][3]=0.f; }

    const float* base = g_x2 + (size_t)(n*64) * HW + p;
    #pragma unroll 4
    for (int ci = 0; ci < 64; ci++) {
        float4 v = *reinterpret_cast<const float4*>(base + (size_t)ci * HW);
        #pragma unroll
        for (int co = 0; co < 8; co++) {
            float wv = sW[co*64 + ci];
            acc[co][0] = fmaf(wv, v.x, acc[co][0]);
            acc[co][1] = fmaf(wv, v.y, acc[co][1]);
            acc[co][2] = fmaf(wv, v.z, acc[co][2]);
            acc[co][3] = fmaf(wv, v.w, acc[co][3]);
        }
    }
    #pragma unroll
    for (int co = 0; co < 8; co++) {
        float4 o = make_float4(fmaxf(acc[co][0], 0.f), fmaxf(acc[co][1], 0.f),
                               fmaxf(acc[co][2], 0.f), fmaxf(acc[co][3], 0.f));
        *reinterpret_cast<float4*>(g_aff + (size_t)(n*8 + co) * HW + p) = o;
    }
}

// ---------------- softmax propagation + blend ----------------
__global__ void k_prop(const float* __restrict__ disp, float* __restrict__ out) {
    int idx = blockIdx.x * blockDim.x + threadIdx.x;
    if (idx >= NB*HW) return;
    int x = idx & 255;
    int y = (idx >> 8) & 255;
    int n = idx >> 16;

    const int dy[8] = { 1, 1, 1, 0, 0, -1, -1, -1 };
    const int dx[8] = { 1, 0,-1, 1,-1,  1,  0, -1 };

    float g[8], dd[8];
    #pragma unroll
    for (int k = 0; k < 8; k++) {
        int yy = y + dy[k], xx = x + dx[k];
        bool ok = (yy >= 0 && yy < H && xx >= 0 && xx < W);
        g[k]  = ok ? g_aff[((size_t)(n*8 + k) * H + yy) * W + xx] : 0.f;
        dd[k] = ok ? disp[((size_t)n * H + yy) * W + xx] : 0.f;
    }
    float m = g[0];
    #pragma unroll
    for (int k = 1; k < 8; k++) m = fmaxf(m, g[k]);
    float se = 0.f, sp = 0.f;
    #pragma unroll
    for (int k = 0; k < 8; k++) {
        float e = expf(g[k] - m);
        se += e;
        sp = fmaf(e, dd[k], sp);
    }
    float prop = sp / se;
    out[idx] = 0.3f * prop + 0.7f * disp[idx];
}

// ---------------- launch ----------------
extern "C" void kernel_launch(void* const* d_in, const int* in_sizes, int n_in,
                              void* d_out, int out_size) {
    const float* normal = (const float*)d_in[0];
    const float* left   = (const float*)d_in[1];
    const float* right  = (const float*)d_in[2];
    const float* disp   = (const float*)d_in[3];
    const float* w1 = (const float*)d_in[4];
    const float* g1 = (const float*)d_in[5];
    const float* b1 = (const float*)d_in[6];
    const float* m1 = (const float*)d_in[7];
    const float* v1 = (const float*)d_in[8];
    const float* w2 = (const float*)d_in[9];
    const float* g2 = (const float*)d_in[10];
    const float* b2 = (const float*)d_in[11];
    const float* m2 = (const float*)d_in[12];
    const float* v2 = (const float*)d_in[13];
    const float* w3 = (const float*)d_in[14];
    float* out = (float*)d_out;

    k_bnfold<<<1, 64>>>(g1, b1, m1, v1, g2, b2, m2, v2);

    int total3 = NB*3*HW;
    k_resize_right<<<(total3 + 255) / 256, 256>>>(right);
    k_feats<<<(total3 + 255) / 256, 256>>>(left, normal, disp);

    k_conv1<<<dim3(8, 8, NB*4), 256>>>(w1);
    k_conv2<<<dim3(8, 8, NB*4), 256>>>(w2);
    k_conv3<<<(NB*HW/4 + 255) / 256, 256>>>(w3);

    k_prop<<<(NB*HW + 255) / 256, 256>>>(disp, out);
}